// round 13
// baseline (speedup 1.0000x reference)
#include <cuda_runtime.h>
#include <cuda_fp16.h>
#include <cstdint>

// Winograd F(4x4,3x3): N=16, Cin=Cout=64, H=W=128, pad=1, nt=32, T=16384.
// Round 12: FULLY FUSED kernel. Each CTA owns 32 tiles (4p x 8q) x all 64 o:
//   phase 1: load x patches, compute BT*d*BT^T once, store all 36 V slices
//            to smem (fp16, 184KB).
//   phase 2: 36 ab-stages: HMMA GEMM (64o x 32t, K=64c) from smem V + smem W
//            (cp.async double-buffered from gmem, L2-resident), fold each
//            M_ab into fp32 register yacc via factorized AT transform.
//   phase 3: bias + direct y stores.
// V and M never touch gmem. Gmem traffic = x(64MB) + y(64MB) + W streams.

#define CH 64
#define ABN 36
#define NT 32

__device__ __half g_Wh[ABN * CH * CH];   // [ab][o][c] fp16, 288KB

__device__ __forceinline__ uint32_t smem_u32(const void* p) {
    uint32_t a;
    asm("{ .reg .u64 t; cvta.to.shared.u64 t, %1; cvt.u32.u64 %0, t; }"
        : "=r"(a) : "l"(p));
    return a;
}

#define CP_ASYNC16(dst, src) \
    asm volatile("cp.async.ca.shared.global [%0], [%1], 16;" \
                 :: "r"(dst), "l"(src) : "memory")
#define CP_COMMIT() asm volatile("cp.async.commit_group;" ::: "memory")
#define CP_WAIT0()  asm volatile("cp.async.wait_group 0;" ::: "memory")

// ---------------------------------------------------------------------------
// K0: weight reorder. src w[o][c][ab] fp32 -> g_Wh[ab][o][c] fp16.
// ---------------------------------------------------------------------------
__global__ void k_wreorder(const float* __restrict__ w) {
    int tid = blockIdx.x * blockDim.x + threadIdx.x;
    if (tid >= ABN * CH * 32) return;
    int i2 = tid & 31;
    int o  = (tid >> 5) & 63;
    int ab = tid >> 11;
    float a0 = w[(o * 64 + i2 * 2) * ABN + ab];
    float a1 = w[(o * 64 + i2 * 2 + 1) * ABN + ab];
    *(__half2*)(g_Wh + ab * (CH * CH) + o * CH + i2 * 2) =
        __floats2half2_rn(a0, a1);
}

// ---------------------------------------------------------------------------
// input transform helper (BT fold over one dim)
// ---------------------------------------------------------------------------
__device__ __forceinline__ void bt_apply(const float d0, const float d1,
                                         const float d2, const float d3,
                                         const float d4, const float d5,
                                         float* out) {
    out[0] = 4.f * d0 - 5.f * d2 + d4;
    out[1] = -4.f * (d1 + d2) + d3 + d4;
    out[2] = 4.f * (d1 - d2) - d3 + d4;
    out[3] = -2.f * d1 - d2 + 2.f * d3 + d4;
    out[4] = 2.f * d1 - d2 - 2.f * d3 + d4;
    out[5] = 4.f * d1 - 5.f * d3 + d5;
}

// ---------------------------------------------------------------------------
// Fused kernel. grid = 512 (16 img x 8 pblk x 4 qblk), block = 256, 1 CTA/SM.
// smem: V[36][64c][40t-pad] fp16 = 184320 B, then W stages 2 x [64][72] fp16
//       = 18432 B. total 202752 B.
// Warp tile: 16o x 16t (8 warps = 4 o-groups x 2 t-groups).
// ---------------------------------------------------------------------------
#define V_ROW_B   80                 // 40 halfs (32 data + 8 pad)
#define V_TILE_B  (64 * V_ROW_B)     // 5120
#define W_OFF     (ABN * V_TILE_B)   // 184320
#define W_ROW_B   144                // 72 halfs (64 data + 8 pad)
#define W_STG_B   (64 * W_ROW_B)     // 9216
#define FUSED_SMEM (W_OFF + 2 * W_STG_B)   // 202752

__global__ __launch_bounds__(256, 1)
void k_fused(const float* __restrict__ x, const float* __restrict__ bias,
             float* __restrict__ y) {
    extern __shared__ char sm[];
    const uint32_t sbase = smem_u32(sm);

    const int tid = threadIdx.x;
    const int wid = tid >> 5;
    const int lid = tid & 31;

    const int n  = blockIdx.x >> 5;
    const int pb = (blockIdx.x >> 2) & 7;   // 8 p-blocks of 4
    const int qb = blockIdx.x & 3;          // 4 q-blocks of 8

    // ---- prologue: issue W stage ab=0 ----
    auto issueW = [&](int ab, int buf) {
        const __half* Wp = g_Wh + ab * (CH * CH);
        uint32_t dstb = sbase + W_OFF + buf * W_STG_B;
#pragma unroll
        for (int it = 0; it < 2; it++) {
            int idx = tid + it * 256;
            int r = idx >> 3, cc = idx & 7;
            CP_ASYNC16(dstb + r * W_ROW_B + cc * 16, Wp + r * 64 + cc * 8);
        }
    };
    issueW(0, 0);
    CP_COMMIT();

    // ---- phase 1: input transform -> smem V ----
    {
        const int tl = tid & 31;                  // tile within block
        const int p  = pb * 4 + (tl >> 3);
        const int q  = qb * 8 + (tl & 7);
        const int r0 = p * 4 - 1;
        const int c0 = q * 4 - 1;
#pragma unroll 1
        for (int k = 0; k < 8; k++) {
            const int c = (tid >> 5) + (k << 3);  // channel 0..63
            const float* xp = x + (((long)n * CH + c) << 14);

            float d[6][6];
#pragma unroll
            for (int i = 0; i < 6; i++) {
                int r = r0 + i;
                bool rv = (r >= 0) && (r < 128);
                const float* row = xp + r * 128;
#pragma unroll
                for (int j = 0; j < 6; j++) {
                    int cc = c0 + j;
                    d[i][j] = (rv && cc >= 0 && cc < 128) ? row[cc] : 0.f;
                }
            }

            float wrow[6][6];
#pragma unroll
            for (int j = 0; j < 6; j++) {
                float t[6];
                bt_apply(d[0][j], d[1][j], d[2][j], d[3][j], d[4][j], d[5][j],
                         t);
#pragma unroll
                for (int a = 0; a < 6; a++) wrow[a][j] = t[a];
            }

            char* vdst = sm + c * V_ROW_B + tl * 2;
#pragma unroll
            for (int a = 0; a < 6; a++) {
                float v[6];
                bt_apply(wrow[a][0], wrow[a][1], wrow[a][2], wrow[a][3],
                         wrow[a][4], wrow[a][5], v);
#pragma unroll
                for (int b = 0; b < 6; b++) {
                    *(__half*)(vdst + (a * 6 + b) * V_TILE_B) =
                        __float2half_rn(v[b]);
                }
            }
        }
    }
    __syncthreads();

    // ---- phase 2: 36 GEMM+fold stages ----
    const int o0w = (wid & 3) * 16;
    const int t0w = (wid >> 2) * 16;

    const float ATm[4][6] = {{1, 1, 1, 1, 1, 0},
                             {0, 1, -1, 2, -2, 0},
                             {0, 1, 1, 4, 4, 0},
                             {0, 1, -1, 8, -8, 1}};

    // 8 cells/thread: cidx = ((oh*2)+nj)*2+tp
    float yacc[8][16];
#pragma unroll
    for (int c = 0; c < 8; c++)
#pragma unroll
        for (int k = 0; k < 16; k++) yacc[c][k] = 0.f;

#pragma unroll
    for (int a = 0; a < 6; a++) {
        float P[8][4];
#pragma unroll
        for (int c = 0; c < 8; c++)
#pragma unroll
            for (int yy = 0; yy < 4; yy++) P[c][yy] = 0.f;

#pragma unroll
        for (int b = 0; b < 6; b++) {
            const int ab = a * 6 + b;

            CP_WAIT0();              // W stage ab landed
            __syncthreads();         // + all readers done with other buffer
            if (ab + 1 < ABN) issueW(ab + 1, (ab + 1) & 1);
            CP_COMMIT();

            const char* Wst = sm + W_OFF + (ab & 1) * W_STG_B;
            const char* Vst = sm + ab * V_TILE_B;

            float acc[2][4] = {{0, 0, 0, 0}, {0, 0, 0, 0}};
#pragma unroll
            for (int ks = 0; ks < 4; ks++) {
                uint32_t a0, a1, a2, a3;
                uint32_t aaddr = smem_u32(
                    Wst + (o0w + (lid & 15)) * W_ROW_B
                        + (ks * 16 + (lid >> 4) * 8) * 2);
                asm volatile(
                    "ldmatrix.sync.aligned.m8n8.x4.shared.b16 "
                    "{%0,%1,%2,%3}, [%4];"
                    : "=r"(a0), "=r"(a1), "=r"(a2), "=r"(a3)
                    : "r"(aaddr));
                uint32_t b0, b1, b2, b3;
                uint32_t baddr = smem_u32(
                    Vst + (ks * 16 + (lid & 15)) * V_ROW_B
                        + (t0w + (lid >> 4) * 8) * 2);
                asm volatile(
                    "ldmatrix.sync.aligned.m8n8.x4.trans.shared.b16 "
                    "{%0,%1,%2,%3}, [%4];"
                    : "=r"(b0), "=r"(b1), "=r"(b2), "=r"(b3)
                    : "r"(baddr));
                asm volatile(
                    "mma.sync.aligned.m16n8k16.row.col.f32.f16.f16.f32 "
                    "{%0,%1,%2,%3}, {%4,%5,%6,%7}, {%8,%9}, {%0,%1,%2,%3};"
                    : "+f"(acc[0][0]), "+f"(acc[0][1]), "+f"(acc[0][2]),
                      "+f"(acc[0][3])
                    : "r"(a0), "r"(a1), "r"(a2), "r"(a3), "r"(b0), "r"(b1));
                asm volatile(
                    "mma.sync.aligned.m16n8k16.row.col.f32.f16.f16.f32 "
                    "{%0,%1,%2,%3}, {%4,%5,%6,%7}, {%8,%9}, {%0,%1,%2,%3};"
                    : "+f"(acc[1][0]), "+f"(acc[1][1]), "+f"(acc[1][2]),
                      "+f"(acc[1][3])
                    : "r"(a0), "r"(a1), "r"(a2), "r"(a3), "r"(b2), "r"(b3));
            }

            // fold b into P. mc[cidx]: cidx=((oh*2)+nj)*2+tp -> acc[nj][oh*2+tp]
#pragma unroll
            for (int yy = 0; yy < 4; yy++) {
                if (ATm[yy][b] != 0.f) {
                    const float cf = ATm[yy][b];
#pragma unroll
                    for (int oh = 0; oh < 2; oh++)
#pragma unroll
                        for (int nj = 0; nj < 2; nj++)
#pragma unroll
                            for (int tp = 0; tp < 2; tp++)
                                P[(oh * 2 + nj) * 2 + tp][yy] +=
                                    cf * acc[nj][oh * 2 + tp];
                }
            }
        }

        // fold a into yacc
#pragma unroll
        for (int xx = 0; xx < 4; xx++) {
            if (ATm[xx][a] != 0.f) {
                const float cf = ATm[xx][a];
#pragma unroll
                for (int c = 0; c < 8; c++)
#pragma unroll
                    for (int yy = 0; yy < 4; yy++)
                        yacc[c][xx * 4 + yy] += cf * P[c][yy];
            }
        }
    }

    // ---- phase 3: bias + store ----
    const int obase = o0w + (lid >> 2);
    const float bv0 = bias[obase];
    const float bv1 = bias[obase + 8];
#pragma unroll
    for (int oh = 0; oh < 2; oh++) {
        int o = obase + oh * 8;
        float bv = oh ? bv1 : bv0;
#pragma unroll
        for (int nj = 0; nj < 2; nj++)
#pragma unroll
            for (int tp = 0; tp < 2; tp++) {
                int cidx = (oh * 2 + nj) * 2 + tp;
                int tl = t0w + nj * 8 + (lid & 3) * 2 + tp;
                int p = pb * 4 + (tl >> 3);
                int q = qb * 8 + (tl & 7);
                float* yp = y + (((size_t)n * CH + o) << 14)
                            + (p * 4) * 128 + q * 4;
#pragma unroll
                for (int xx = 0; xx < 4; xx++) {
                    float4 v = make_float4(yacc[cidx][xx * 4 + 0] + bv,
                                           yacc[cidx][xx * 4 + 1] + bv,
                                           yacc[cidx][xx * 4 + 2] + bv,
                                           yacc[cidx][xx * 4 + 3] + bv);
                    *(float4*)(yp + xx * 128) = v;
                }
            }
    }
}

// ---------------------------------------------------------------------------
extern "C" void kernel_launch(void* const* d_in, const int* in_sizes, int n_in,
                              void* d_out, int out_size) {
    const float* x    = (const float*)d_in[0];
    const float* w    = (const float*)d_in[1];
    const float* bias = (const float*)d_in[2];
    float* y = (float*)d_out;

    cudaFuncSetAttribute(k_fused, cudaFuncAttributeMaxDynamicSharedMemorySize,
                         FUSED_SMEM);

    k_wreorder<<<(ABN * CH * 32 + 255) / 256, 256>>>(w);
    k_fused<<<512, 256, FUSED_SMEM>>>(x, bias, y);
}

// round 15
// speedup vs baseline: 1.2065x; 1.2065x over previous
#include <cuda_runtime.h>
#include <cuda_fp16.h>
#include <cstdint>

// Winograd F(4x4,3x3): N=16, Cin=Cout=64, H=W=128, pad=1, nt=32, T=16384.
// Round 15: r11 + b-fold moved into K2's epilogue. Intermediate shrinks
// from 36 M-slices (75.5MB) to 24 P-slices (50.3MB); K3 is a pure a-fold.
//
//   K0: weight (o,i,ab) fp32 -> g_Wh[ab][o][i] fp16
//   K1: input transform x -> g_Vh[ab][i][t] fp16    (t = n*1024 + p*32 + q)
//   K2: CTA=(a, 64t): loop b=0..5 { HMMA M_ab (64o x 64t, K=64);
//       P[yy] += AT[yy][b]*M (fp32 regs) } -> g_Ph[(a*4+yy)][o][t] fp16
//   K3: y[x][yy] = sum_a AT[x][a]*P_a[yy] + bias -> y fp32

#define TQ 16384
#define CH 64
#define ABN 36
#define VSLICE (CH * TQ)

__device__ __half g_Vh[ABN * CH * TQ];   // 75.5 MB
__device__ __half g_Ph[24 * CH * TQ];    // 50.3 MB
__device__ __half g_Wh[ABN * CH * CH];

__device__ __forceinline__ uint32_t smem_u32(const void* p) {
    uint32_t a;
    asm("{ .reg .u64 t; cvta.to.shared.u64 t, %1; cvt.u32.u64 %0, t; }"
        : "=r"(a) : "l"(p));
    return a;
}

#define CP_ASYNC16(dst, src) \
    asm volatile("cp.async.ca.shared.global [%0], [%1], 16;" \
                 :: "r"(dst), "l"(src) : "memory")
#define CP_COMMIT() asm volatile("cp.async.commit_group;" ::: "memory")
#define CP_WAIT0()  asm volatile("cp.async.wait_group 0;" ::: "memory")

// ---------------------------------------------------------------------------
// K0: weight reorder. src w[o][i][ab] fp32 -> g_Wh[ab][o][i] fp16.
// ---------------------------------------------------------------------------
__global__ void k_wreorder(const float* __restrict__ w) {
    int tid = blockIdx.x * blockDim.x + threadIdx.x;
    if (tid >= ABN * CH * 32) return;
    int i2 = tid & 31;
    int o  = (tid >> 5) & 63;
    int ab = tid >> 11;
    float a0 = w[(o * 64 + i2 * 2) * ABN + ab];
    float a1 = w[(o * 64 + i2 * 2 + 1) * ABN + ab];
    *(__half2*)(g_Wh + ab * (CH * CH) + o * CH + i2 * 2) =
        __floats2half2_rn(a0, a1);
}

// ---------------------------------------------------------------------------
// K1: input transform -> g_Vh[ab][c][t] fp16
// ---------------------------------------------------------------------------
__device__ __forceinline__ void bt_apply(const float d0, const float d1,
                                         const float d2, const float d3,
                                         const float d4, const float d5,
                                         float* out) {
    out[0] = 4.f * d0 - 5.f * d2 + d4;
    out[1] = -4.f * (d1 + d2) + d3 + d4;
    out[2] = 4.f * (d1 - d2) - d3 + d4;
    out[3] = -2.f * d1 - d2 + 2.f * d3 + d4;
    out[4] = 2.f * d1 - d2 - 2.f * d3 + d4;
    out[5] = 4.f * d1 - 5.f * d3 + d5;
}

__global__ __launch_bounds__(256)
void k_input_transform(const float* __restrict__ x) {
    int tid = blockIdx.x * blockDim.x + threadIdx.x;
    int q = tid & 31;
    int p = (tid >> 5) & 31;
    int c = (tid >> 10) & 63;
    int n = tid >> 16;

    const float* xp = x + (((long)n * CH + c) << 14);
    int r0 = p * 4 - 1;
    int c0 = q * 4 - 1;

    float d[6][6];
#pragma unroll
    for (int i = 0; i < 6; i++) {
        int r = r0 + i;
        bool rv = (r >= 0) && (r < 128);
        const float* row = xp + r * 128;
#pragma unroll
        for (int j = 0; j < 6; j++) {
            int cc = c0 + j;
            d[i][j] = (rv && cc >= 0 && cc < 128) ? row[cc] : 0.f;
        }
    }

    float wrow[6][6];
#pragma unroll
    for (int j = 0; j < 6; j++) {
        float t[6];
        bt_apply(d[0][j], d[1][j], d[2][j], d[3][j], d[4][j], d[5][j], t);
#pragma unroll
        for (int a = 0; a < 6; a++) wrow[a][j] = t[a];
    }

    int t = (n << 10) + (p << 5) + q;
    int base = c * TQ + t;
#pragma unroll
    for (int a = 0; a < 6; a++) {
        float v[6];
        bt_apply(wrow[a][0], wrow[a][1], wrow[a][2], wrow[a][3], wrow[a][4],
                 wrow[a][5], v);
#pragma unroll
        for (int b = 0; b < 6; b++) {
            g_Vh[(a * 6 + b) * VSLICE + base] = __float2half_rn(v[b]);
        }
    }
}

// ---------------------------------------------------------------------------
// K2: HMMA GEMM with b-fold. grid = (TQ/64 = 256, 6a), block = 256 (8 warps),
// 2 CTAs/SM. CTA tile: 64o x 64t; warp tile 16o x 32t (o-group=wid&3,
// t-group=wid>>2). Loop b=0..5: load W,V slice for ab=a*6+b (depth-1
// double-buffered cp.async, issued one full stage ahead), GEMM K=64,
// fold into P[nj][r][yy] fp32 regs. Epilogue: per yy, stage P into smem,
// write 128B coalesced rows to g_Ph.
// ---------------------------------------------------------------------------
__global__ __launch_bounds__(256, 2)
void k_gemm_fold() {
    __shared__ __half Wst[2][64][72];   // [buf][o][c]
    __shared__ __half Vst[2][64][72];   // [buf][c][t]; buf0 reused as staging

    const int tid = threadIdx.x;
    const int wid = tid >> 5;
    const int lid = tid & 31;
    const int a  = blockIdx.y;           // 0..5
    const int tb = blockIdx.x * 64;

    const int ld_r = tid >> 3;           // 0..31 (x2 iters -> 0..63)
    const int ld_c = (tid & 7) * 8;

    auto issue = [&](int b, int buf) {
        const int ab = a * 6 + b;
        const __half* Wp = g_Wh + ab * (CH * CH);
        const __half* Vp = g_Vh + ab * VSLICE + tb;
#pragma unroll
        for (int it = 0; it < 2; it++) {
            int r = ld_r + it * 32;
            CP_ASYNC16(smem_u32(&Wst[buf][r][ld_c]), Wp + r * 64 + ld_c);
            CP_ASYNC16(smem_u32(&Vst[buf][r][ld_c]),
                       Vp + (size_t)r * TQ + ld_c);
        }
    };

    issue(0, 0);
    CP_COMMIT();

    const int o0 = (wid & 3) * 16;
    const int t0 = (wid >> 2) * 32;

    const float ATb[4][6] = {{1, 1, 1, 1, 1, 0},
                             {0, 1, -1, 2, -2, 0},
                             {0, 1, 1, 4, 4, 0},
                             {0, 1, -1, 8, -8, 1}};

    float P[4][4][4];                    // [nj][reg][yy]
#pragma unroll
    for (int nj = 0; nj < 4; nj++)
#pragma unroll
        for (int r = 0; r < 4; r++)
#pragma unroll
            for (int yy = 0; yy < 4; yy++) P[nj][r][yy] = 0.f;

#pragma unroll
    for (int b = 0; b < 6; b++) {
        CP_WAIT0();                      // stage b landed (issued 1 iter ago)
        __syncthreads();                 // + all readers done with buf (b-1)
        if (b + 1 < 6) issue(b + 1, (b + 1) & 1);
        CP_COMMIT();

        const int s = b & 1;
        float acc[4][4];
#pragma unroll
        for (int nj = 0; nj < 4; nj++)
#pragma unroll
            for (int r = 0; r < 4; r++) acc[nj][r] = 0.f;

#pragma unroll
        for (int ks = 0; ks < 4; ks++) {
            const int k0 = ks * 16;
            uint32_t a0, a1, a2, a3;
            uint32_t aaddr = smem_u32(
                &Wst[s][o0 + (lid & 15)][k0 + (lid >> 4) * 8]);
            asm volatile(
                "ldmatrix.sync.aligned.m8n8.x4.shared.b16 {%0,%1,%2,%3}, [%4];"
                : "=r"(a0), "=r"(a1), "=r"(a2), "=r"(a3)
                : "r"(aaddr));
            uint32_t rb[4][2];
#pragma unroll
            for (int njp = 0; njp < 2; njp++) {
                uint32_t baddr = smem_u32(
                    &Vst[s][k0 + (lid & 15)][t0 + njp * 16 + (lid >> 4) * 8]);
                uint32_t b0, b1, b2, b3;
                asm volatile(
                    "ldmatrix.sync.aligned.m8n8.x4.trans.shared.b16 "
                    "{%0,%1,%2,%3}, [%4];"
                    : "=r"(b0), "=r"(b1), "=r"(b2), "=r"(b3)
                    : "r"(baddr));
                rb[njp * 2][0] = b0; rb[njp * 2][1] = b1;
                rb[njp * 2 + 1][0] = b2; rb[njp * 2 + 1][1] = b3;
            }
#pragma unroll
            for (int nj = 0; nj < 4; nj++) {
                asm volatile(
                    "mma.sync.aligned.m16n8k16.row.col.f32.f16.f16.f32 "
                    "{%0,%1,%2,%3}, {%4,%5,%6,%7}, {%8,%9}, {%0,%1,%2,%3};"
                    : "+f"(acc[nj][0]), "+f"(acc[nj][1]), "+f"(acc[nj][2]),
                      "+f"(acc[nj][3])
                    : "r"(a0), "r"(a1), "r"(a2), "r"(a3),
                      "r"(rb[nj][0]), "r"(rb[nj][1]));
            }
        }

        // fold b into P (structural zeros skipped; coefs compile-time)
#pragma unroll
        for (int yy = 0; yy < 4; yy++) {
            if (ATb[yy][b] != 0.f) {
                const float cf = ATb[yy][b];
#pragma unroll
                for (int nj = 0; nj < 4; nj++)
#pragma unroll
                    for (int r = 0; r < 4; r++)
                        P[nj][r][yy] += cf * acc[nj][r];
            }
        }
    }

    // Epilogue: per yy, stage into Vst[0] then 128B coalesced row stores.
    __syncthreads();
    __half (*Ps)[72] = Vst[0];
#pragma unroll
    for (int yy = 0; yy < 4; yy++) {
        int orow = o0 + (lid >> 2);
#pragma unroll
        for (int nj = 0; nj < 4; nj++) {
            int tl = t0 + nj * 8 + (lid & 3) * 2;
            *(__half2*)&Ps[orow][tl] =
                __floats2half2_rn(P[nj][0][yy], P[nj][1][yy]);
            *(__half2*)&Ps[orow + 8][tl] =
                __floats2half2_rn(P[nj][2][yy], P[nj][3][yy]);
        }
        __syncthreads();

        __half* Pp = g_Ph + (size_t)(a * 4 + yy) * VSLICE + tb;
#pragma unroll
        for (int pass = 0; pass < 8; pass++) {
            int row = pass * 8 + wid;
            *(uint32_t*)(Pp + (size_t)row * TQ + lid * 2) =
                *(const uint32_t*)&Ps[row][lid * 2];
        }
        __syncthreads();
    }
}

// ---------------------------------------------------------------------------
// K3: a-fold + bias. 2 t per thread (half2 loads, float2 math).
// y[x][yy] = sum_a AT[x][a] * P[a][yy].
// ---------------------------------------------------------------------------
__global__ __launch_bounds__(256)
void k_output_transform(const float* __restrict__ bias,
                        float* __restrict__ y) {
    int tid = blockIdx.x * blockDim.x + threadIdx.x;
    int q2 = tid & 15;
    int p  = (tid >> 4) & 31;
    int o  = (tid >> 9) & 63;
    int n  = tid >> 15;

    int t = (n << 10) + (p << 5) + (q2 << 1);
    const __half* Pb = g_Ph + o * TQ + t;

    float2 u[4][4];     // [x][yy]
#pragma unroll
    for (int yy = 0; yy < 4; yy++) {
        float2 m[6];
#pragma unroll
        for (int a = 0; a < 6; a++)
            m[a] = __half22float2(
                *(const __half2*)(Pb + (size_t)(a * 4 + yy) * VSLICE));
        u[0][yy].x = m[0].x + m[1].x + m[2].x + m[3].x + m[4].x;
        u[0][yy].y = m[0].y + m[1].y + m[2].y + m[3].y + m[4].y;
        u[1][yy].x = m[1].x - m[2].x + 2.f * (m[3].x - m[4].x);
        u[1][yy].y = m[1].y - m[2].y + 2.f * (m[3].y - m[4].y);
        u[2][yy].x = m[1].x + m[2].x + 4.f * (m[3].x + m[4].x);
        u[2][yy].y = m[1].y + m[2].y + 4.f * (m[3].y + m[4].y);
        u[3][yy].x = m[1].x - m[2].x + 8.f * (m[3].x - m[4].x) + m[5].x;
        u[3][yy].y = m[1].y - m[2].y + 8.f * (m[3].y - m[4].y) + m[5].y;
    }

    float bv = bias[o];
    float* yp = y + (((size_t)n * CH + o) << 14) + (p * 4) * 128 + (q2 << 3);
#pragma unroll
    for (int xx = 0; xx < 4; xx++) {
        float4 v0 = make_float4(u[xx][0].x + bv, u[xx][1].x + bv,
                                u[xx][2].x + bv, u[xx][3].x + bv);
        float4 v1 = make_float4(u[xx][0].y + bv, u[xx][1].y + bv,
                                u[xx][2].y + bv, u[xx][3].y + bv);
        *(float4*)(yp + xx * 128) = v0;
        *(float4*)(yp + xx * 128 + 4) = v1;
    }
}

// ---------------------------------------------------------------------------
extern "C" void kernel_launch(void* const* d_in, const int* in_sizes, int n_in,
                              void* d_out, int out_size) {
    const float* x    = (const float*)d_in[0];
    const float* w    = (const float*)d_in[1];
    const float* bias = (const float*)d_in[2];
    float* y = (float*)d_out;

    k_wreorder<<<(ABN * CH * 32 + 255) / 256, 256>>>(w);
    k_input_transform<<<4096, 256>>>(x);
    dim3 g2(TQ / 64, 6);
    k_gemm_fold<<<g2, 256>>>();
    k_output_transform<<<2048, 256>>>(bias, y);
}